// round 2
// baseline (speedup 1.0000x reference)
#include <cuda_runtime.h>

#define KDIM 128

// Zero-initialized device scratch (re-zeroed by the last block each launch,
// so every graph replay starts from a clean state).
__device__ float g_u[KDIM];
__device__ float g_t[KDIM];
__device__ float g_s[KDIM];
__device__ float g_bias;
__device__ float g_sqsum;
__device__ unsigned int g_count;

__device__ __forceinline__ void process_idx(
    int idx, float val, int n, int m,
    const float* __restrict__ w_bias,
    const float* __restrict__ uV,
    const float* __restrict__ tV,
    const float* __restrict__ bV)
{
    atomicAdd(&g_bias, val * __ldg(&w_bias[idx]));
    if (idx < n) {
        const float4* row = (const float4*)(uV + (size_t)idx * KDIM);
        #pragma unroll
        for (int k = 0; k < KDIM / 4; ++k) {
            float4 r = __ldg(&row[k]);
            atomicAdd(&g_u[4 * k + 0], val * r.x);
            atomicAdd(&g_u[4 * k + 1], val * r.y);
            atomicAdd(&g_u[4 * k + 2], val * r.z);
            atomicAdd(&g_u[4 * k + 3], val * r.w);
        }
    } else if (idx < n + m) {
        const float4* row = (const float4*)(tV + (size_t)(idx - n) * KDIM);
        #pragma unroll
        for (int k = 0; k < KDIM / 4; ++k) {
            float4 r = __ldg(&row[k]);
            atomicAdd(&g_t[4 * k + 0], val * r.x);
            atomicAdd(&g_t[4 * k + 1], val * r.y);
            atomicAdd(&g_t[4 * k + 2], val * r.z);
            atomicAdd(&g_t[4 * k + 3], val * r.w);
        }
    } else {
        const float4* row = (const float4*)(bV + (size_t)(idx - n - m) * KDIM);
        float sq = 0.f;
        #pragma unroll
        for (int k = 0; k < KDIM / 4; ++k) {
            float4 r = __ldg(&row[k]);
            atomicAdd(&g_s[4 * k + 0], val * r.x);
            atomicAdd(&g_s[4 * k + 1], val * r.y);
            atomicAdd(&g_s[4 * k + 2], val * r.z);
            atomicAdd(&g_s[4 * k + 3], val * r.w);
            sq += r.x * r.x + r.y * r.y + r.z * r.z + r.w * r.w;
        }
        atomicAdd(&g_sqsum, val * sq);
    }
}

__device__ __forceinline__ bool process_vec(
    int i, float4 v, int n, int m,
    const float* __restrict__ w_bias,
    const float* __restrict__ uV,
    const float* __restrict__ tV,
    const float* __restrict__ bV)
{
    if (v.x == 0.f && v.y == 0.f && v.z == 0.f && v.w == 0.f) return false;
    if (v.x != 0.f) process_idx(4 * i + 0, v.x, n, m, w_bias, uV, tV, bV);
    if (v.y != 0.f) process_idx(4 * i + 1, v.y, n, m, w_bias, uV, tV, bV);
    if (v.z != 0.f) process_idx(4 * i + 2, v.z, n, m, w_bias, uV, tV, bV);
    if (v.w != 0.f) process_idx(4 * i + 3, v.w, n, m, w_bias, uV, tV, bV);
    return true;
}

__global__ void fm_loss_kernel(
    const float* __restrict__ x,
    const float* __restrict__ delta,
    const float* __restrict__ w0,
    const float* __restrict__ w_bias,
    const float* __restrict__ uV,
    const float* __restrict__ tV,
    const float* __restrict__ bV,
    float* __restrict__ out,
    int n, int m)
{
    const int p = n + 2 * m;
    const int p4 = p >> 2;
    const int tid = blockIdx.x * blockDim.x + threadIdx.x;
    const int N = gridDim.x * blockDim.x;

    // Phase 1: sparse scan of x[:p], 4 independent (front-batched) float4
    // loads per thread for MLP=4. Grid is sized so 4*N covers p4.
    const float4* x4 = (const float4*)x;
    const int i0 = tid;
    const int i1 = tid + N;
    const int i2 = tid + 2 * N;
    const int i3 = tid + 3 * N;
    float4 v0 = make_float4(0.f, 0.f, 0.f, 0.f);
    float4 v1 = v0, v2 = v0, v3 = v0;
    if (i0 < p4) v0 = x4[i0];
    if (i1 < p4) v1 = x4[i1];
    if (i2 < p4) v2 = x4[i2];
    if (i3 < p4) v3 = x4[i3];

    bool did = false;
    did |= process_vec(i0, v0, n, m, w_bias, uV, tV, bV);
    did |= process_vec(i1, v1, n, m, w_bias, uV, tV, bV);
    did |= process_vec(i2, v2, n, m, w_bias, uV, tV, bV);
    did |= process_vec(i3, v3, n, m, w_bias, uV, tV, bV);

    // scalar tail (p % 4 != 0 safety; empty for this problem)
    for (int i = (p4 << 2) + tid; i < p; i += N) {
        float v = x[i];
        if (v != 0.f) { process_idx(i, v, n, m, w_bias, uV, tV, bV); did = true; }
    }

    // Phase 2: last-block-done detection. Only threads that issued global
    // accumulation atomics pay the gpu-scope fence.
    if (did) __threadfence();
    __syncthreads();
    __shared__ bool s_last;
    if (threadIdx.x == 0) {
        __threadfence();
        s_last = (atomicAdd(&g_count, 1u) == gridDim.x - 1);
    }
    __syncthreads();
    if (!s_last) return;
    __threadfence();  // acquire: make all blocks' scratch writes visible

    // Phase 3: finalize (4 dot products over K=128, warp-shuffle reduce)
    __shared__ float s_part[4][4];
    float ut = 0.f, ts = 0.f, us = 0.f, ss = 0.f;
    if (threadIdx.x < KDIM) {
        float u = g_u[threadIdx.x];
        float t = g_t[threadIdx.x];
        float s = g_s[threadIdx.x];
        ut = u * t; ts = t * s; us = u * s; ss = s * s;
    }
    #pragma unroll
    for (int off = 16; off > 0; off >>= 1) {
        ut += __shfl_down_sync(0xffffffff, ut, off);
        ts += __shfl_down_sync(0xffffffff, ts, off);
        us += __shfl_down_sync(0xffffffff, us, off);
        ss += __shfl_down_sync(0xffffffff, ss, off);
    }
    const int warp = threadIdx.x >> 5;
    const int lane = threadIdx.x & 31;
    if (lane == 0 && warp < 4) {
        s_part[0][warp] = ut;
        s_part[1][warp] = ts;
        s_part[2][warp] = us;
        s_part[3][warp] = ss;
    }
    __syncthreads();
    if (threadIdx.x == 0) {
        float UT = 0.f, TS = 0.f, US = 0.f, SS = 0.f;
        #pragma unroll
        for (int w = 0; w < 4; ++w) {
            UT += s_part[0][w];
            TS += s_part[1][w];
            US += s_part[2][w];
            SS += s_part[3][w];
        }
        float y = w0[0] + g_bias + UT + TS + 0.5f * (SS - g_sqsum) + US;
        float z = y * delta[0];
        // -log_sigmoid(z) = max(-z, 0) + log1p(exp(-|z|))
        out[0] = fmaxf(-z, 0.f) + log1pf(expf(-fabsf(z)));
        // reset scalar scratch for the next replay
        g_bias = 0.f;
        g_sqsum = 0.f;
        g_count = 0u;
    }
    __syncthreads();
    if (threadIdx.x < KDIM) {
        g_u[threadIdx.x] = 0.f;
        g_t[threadIdx.x] = 0.f;
        g_s[threadIdx.x] = 0.f;
    }
}

extern "C" void kernel_launch(void* const* d_in, const int* in_sizes, int n_in,
                              void* d_out, int out_size) {
    const float* x      = (const float*)d_in[0];
    const float* delta  = (const float*)d_in[1];
    // d_in[2] = pmi (unused by the reference)
    const float* w0     = (const float*)d_in[3];
    const float* w_bias = (const float*)d_in[4];
    const float* uV     = (const float*)d_in[5];
    const float* tV     = (const float*)d_in[6];
    const float* bV     = (const float*)d_in[7];
    float* out = (float*)d_out;

    const int n = in_sizes[5] / KDIM;   // u_V is (n, 128)
    const int m = in_sizes[6] / KDIM;   // t_V is (m, 128)
    const int p = n + 2 * m;

    const int threads = 256;
    const int p4 = p >> 2;
    const int per_block = threads * 4;           // 4 float4 loads per thread
    int blocks = (p4 + per_block - 1) / per_block;
    if (blocks < 1) blocks = 1;

    fm_loss_kernel<<<blocks, threads>>>(x, delta, w0, w_bias, uV, tV, bV, out, n, m);
}

// round 5
// speedup vs baseline: 1.1366x; 1.1366x over previous
#include <cuda_runtime.h>

#define KDIM 128
#define MAXNNZ 256

// Zero-initialized device scratch; the last block resets the two scalars each
// launch so every graph replay starts clean.
__device__ int          g_nnz;
__device__ unsigned int g_count;
__device__ int          g_idx[MAXNNZ];
__device__ float        g_val[MAXNNZ];

__device__ __forceinline__ bool emit_nnz(int idx, float val) {
    int slot = atomicAdd(&g_nnz, 1);
    if (slot < MAXNNZ) {
        g_idx[slot] = idx;
        g_val[slot] = val;
    }
    return true;
}

__global__ void fm_loss_kernel(
    const float* __restrict__ x,
    const float* __restrict__ delta,
    const float* __restrict__ w0,
    const float* __restrict__ w_bias,
    const float* __restrict__ uV,
    const float* __restrict__ tV,
    const float* __restrict__ bV,
    float* __restrict__ out,
    int n, int m)
{
    const int p  = n + 2 * m;
    const int p4 = p >> 2;
    const int tid = blockIdx.x * blockDim.x + threadIdx.x;
    const int N   = gridDim.x * blockDim.x;

    // ---- Phase 1: sparse scan of x[:p]; emit (idx, val) only. No math. ----
    bool wrote = false;
    if (tid < p4) {
        float4 v = ((const float4*)x)[tid];
        if (v.x != 0.f || v.y != 0.f || v.z != 0.f || v.w != 0.f) {
            if (v.x != 0.f) wrote |= emit_nnz(4 * tid + 0, v.x);
            if (v.y != 0.f) wrote |= emit_nnz(4 * tid + 1, v.y);
            if (v.z != 0.f) wrote |= emit_nnz(4 * tid + 2, v.z);
            if (v.w != 0.f) wrote |= emit_nnz(4 * tid + 3, v.w);
        }
    }
    for (int i = (p4 << 2) + tid; i < p; i += N) {   // tail (p % 4)
        float v = x[i];
        if (v != 0.f) wrote |= emit_nnz(i, v);
    }

    // ---- Phase 2: last-block-done ----
    if (wrote) __threadfence();       // release: list writes visible
    __syncthreads();
    __shared__ bool s_last;
    if (threadIdx.x == 0) {
        __threadfence();
        s_last = (atomicAdd(&g_count, 1u) == gridDim.x - 1);
    }
    __syncthreads();
    if (!s_last) return;
    __threadfence();                  // acquire

    // ---- Phase 3: last block gathers rows and computes everything ----
    const int k   = threadIdx.x & (KDIM - 1);   // dimension 0..127
    const int grp = threadIdx.x >> 7;           // entry-group 0/1

    __shared__ const float* s_ptr[MAXNNZ];
    __shared__ float        s_v[MAXNNZ];
    __shared__ int          s_ty[MAXNNZ];
    __shared__ float        s_bias;
    __shared__ float        s_pu[KDIM], s_pt[KDIM], s_ps[KDIM], s_psq[KDIM];
    __shared__ float        s_red[4][5];

    int nnz = g_nnz;
    if (nnz > MAXNNZ) nnz = MAXNNZ;

    if (threadIdx.x == 0) s_bias = 0.f;
    __syncthreads();

    if (threadIdx.x < nnz) {
        int   idx = g_idx[threadIdx.x];
        float val = g_val[threadIdx.x];
        const float* base; int ty;
        if (idx < n)          { base = uV + (size_t)idx * KDIM;            ty = 0; }
        else if (idx < n + m) { base = tV + (size_t)(idx - n) * KDIM;      ty = 1; }
        else                  { base = bV + (size_t)(idx - n - m) * KDIM;  ty = 2; }
        s_ptr[threadIdx.x] = base;
        s_v[threadIdx.x]   = val;
        s_ty[threadIdx.x]  = ty;
        atomicAdd(&s_bias, val * __ldg(&w_bias[idx]));
    }
    __syncthreads();

    // Per-dimension accumulation: each group handles entries j ≡ grp (mod 2).
    // Inner body is one unconditional coalesced LDG -> MLP via unroll.
    float u = 0.f, t = 0.f, s = 0.f, sq = 0.f;

#define FM_PROC(jj)                                            \
    {                                                          \
        float b   = __ldg(s_ptr[jj] + k);                      \
        float val = s_v[jj];                                   \
        int   ty  = s_ty[jj];                                  \
        float f   = val * b;                                   \
        if (ty == 0)      u  += f;                             \
        else if (ty == 1) t  += f;                             \
        else              { s += f; sq += f * b; }             \
    }

    int j = grp;
    for (; j + 6 < nnz; j += 8) {
        FM_PROC(j); FM_PROC(j + 2); FM_PROC(j + 4); FM_PROC(j + 6);
    }
    for (; j < nnz; j += 2) FM_PROC(j);
#undef FM_PROC

    // Combine the two entry-groups.
    if (grp == 1) { s_pu[k] = u; s_pt[k] = t; s_ps[k] = s; s_psq[k] = sq; }
    __syncthreads();

    if (grp == 0) {
        u  += s_pu[k];
        t  += s_pt[k];
        s  += s_ps[k];
        sq += s_psq[k];
        float ut = u * t, ts = t * s, us = u * s, ss = s * s;
        #pragma unroll
        for (int off = 16; off > 0; off >>= 1) {
            ut += __shfl_down_sync(0xffffffff, ut, off);
            ts += __shfl_down_sync(0xffffffff, ts, off);
            us += __shfl_down_sync(0xffffffff, us, off);
            ss += __shfl_down_sync(0xffffffff, ss, off);
            sq += __shfl_down_sync(0xffffffff, sq, off);
        }
        const int warp = threadIdx.x >> 5;   // 0..3
        const int lane = threadIdx.x & 31;
        if (lane == 0) {
            s_red[warp][0] = ut; s_red[warp][1] = ts; s_red[warp][2] = us;
            s_red[warp][3] = ss; s_red[warp][4] = sq;
        }
    }
    __syncthreads();

    if (threadIdx.x == 0) {
        float UT = 0.f, TS = 0.f, US = 0.f, SS = 0.f, SQ = 0.f;
        #pragma unroll
        for (int w = 0; w < 4; ++w) {
            UT += s_red[w][0]; TS += s_red[w][1]; US += s_red[w][2];
            SS += s_red[w][3]; SQ += s_red[w][4];
        }
        float y = w0[0] + s_bias + UT + TS + 0.5f * (SS - SQ) + US;
        float z = y * delta[0];
        // -log_sigmoid(z) = max(-z, 0) + log1p(exp(-|z|))
        out[0] = fmaxf(-z, 0.f) + log1pf(expf(-fabsf(z)));
        // reset scratch for next graph replay
        g_nnz   = 0;
        g_count = 0u;
    }
}

extern "C" void kernel_launch(void* const* d_in, const int* in_sizes, int n_in,
                              void* d_out, int out_size) {
    const float* x      = (const float*)d_in[0];
    const float* delta  = (const float*)d_in[1];
    // d_in[2] = pmi (unused by the reference)
    const float* w0     = (const float*)d_in[3];
    const float* w_bias = (const float*)d_in[4];
    const float* uV     = (const float*)d_in[5];
    const float* tV     = (const float*)d_in[6];
    const float* bV     = (const float*)d_in[7];
    float* out = (float*)d_out;

    const int n = in_sizes[5] / KDIM;   // u_V is (n, 128)
    const int m = in_sizes[6] / KDIM;   // t_V is (m, 128)
    const int p = n + 2 * m;

    const int threads = 256;
    const int p4 = p >> 2;
    int blocks = (p4 + threads - 1) / threads;
    if (blocks < 1) blocks = 1;

    fm_loss_kernel<<<blocks, threads>>>(x, delta, w0, w_bias, uV, tV, bV, out, n, m);
}